// round 7
// baseline (speedup 1.0000x reference)
#include <cuda_runtime.h>
#include <math.h>
#include <stdint.h>

#define NLAYERS 2
#define HID 2048
#define NHEADS 8
#define HEADDIM 256
#define FFDIM 8192
#define NBATCH 4
#define SEQ 1024
#define NTOK (NBATCH * SEQ)   // 4096
#define LNEPS 1e-5f

// ---------------- scratch (static device globals; no allocation at runtime) ----------------
__device__ float g_x  [NTOK * HID];
__device__ float g_xn [NTOK * HID];
__device__ float g_q  [NTOK * HID];
__device__ float g_k  [NTOK * HID];
__device__ float g_v  [NTOK * HID];
__device__ float g_g  [NTOK * HID];
__device__ float g_y  [NTOK * HID];
__device__ float g_ret[NTOK * HID];
__device__ float g_rn [NTOK * HID];
__device__ float g_scores[(size_t)NBATCH * NHEADS * SEQ * SEQ];  // 134 MB
__device__ float g_mid[(size_t)NTOK * FFDIM];                    // 134 MB

// by-value pointer bundles for the fused 4-projection launch
struct Ptr4  { const float* p[4]; };
struct OPtr4 { float*       p[4]; };

#define GEMM_STG 2560                        // floats per stage per operand
#define GEMM_SMEM_BYTES (3 * GEMM_STG * 2 * 4)   // 61440 B dynamic smem

// ---------------- helpers ----------------
__device__ __forceinline__ float warp_sum(float v) {
#pragma unroll
    for (int o = 16; o > 0; o >>= 1) v += __shfl_down_sync(0xffffffffu, v, o);
    return v;
}

__device__ __forceinline__ void split_tf32(float a, uint32_t& hi, uint32_t& lo) {
    uint32_t h;
    asm("cvt.rna.tf32.f32 %0, %1;" : "=r"(h) : "f"(a));
    float r = a - __uint_as_float(h);
    uint32_t l;
    asm("cvt.rna.tf32.f32 %0, %1;" : "=r"(l) : "f"(r));
    hi = h; lo = l;
}

__device__ __forceinline__ void mma_tf32(float* c, const uint32_t* a, const uint32_t* b) {
    asm volatile(
        "mma.sync.aligned.m16n8k8.row.col.f32.tf32.tf32.f32 "
        "{%0,%1,%2,%3}, {%4,%5,%6,%7}, {%8,%9}, {%0,%1,%2,%3};"
        : "+f"(c[0]), "+f"(c[1]), "+f"(c[2]), "+f"(c[3])
        : "r"(a[0]), "r"(a[1]), "r"(a[2]), "r"(a[3]), "r"(b[0]), "r"(b[1]));
}

__device__ __forceinline__ void cp16(void* smem_dst, const void* gmem_src) {
    uint32_t d = (uint32_t)__cvta_generic_to_shared(smem_dst);
    asm volatile("cp.async.cg.shared.global [%0], [%1], 16;\n" :: "r"(d), "l"(gmem_src));
}
__device__ __forceinline__ void cp_commit() { asm volatile("cp.async.commit_group;\n"); }
__device__ __forceinline__ void cp_wait1()  { asm volatile("cp.async.wait_group 1;\n"); }
__device__ __forceinline__ void cp_wait0()  { asm volatile("cp.async.wait_group 0;\n"); }

// ---------------- LayerNorm over HID channels, one block per token ----------------
__global__ void __launch_bounds__(256) ln_kernel(const float* __restrict__ x,
                                                 const float* __restrict__ gamma,
                                                 const float* __restrict__ beta,
                                                 float* __restrict__ out) {
    int row = blockIdx.x;
    const float* xr = x + (size_t)row * HID;
    float lv[8];
    float s = 0.f, sq = 0.f;
#pragma unroll
    for (int i = 0; i < 8; i++) {
        float v = xr[threadIdx.x + i * 256];
        lv[i] = v; s += v; sq += v * v;
    }
    s = warp_sum(s); sq = warp_sum(sq);
    __shared__ float sh0[8], sh1[8];
    int warp = threadIdx.x >> 5, lane = threadIdx.x & 31;
    if (lane == 0) { sh0[warp] = s; sh1[warp] = sq; }
    __syncthreads();
    float S = 0.f, SQ = 0.f;
#pragma unroll
    for (int w = 0; w < 8; w++) { S += sh0[w]; SQ += sh1[w]; }
    float mu  = S * (1.f / HID);
    float var = SQ * (1.f / HID) - mu * mu;
    float inv = rsqrtf(var + LNEPS);
    float* orow = out + (size_t)row * HID;
#pragma unroll
    for (int i = 0; i < 8; i++) {
        int c = threadIdx.x + i * 256;
        orow[c] = (lv[i] - mu) * inv * gamma[c] + beta[c];
    }
}

// ---------------- GroupNorm (per token, per head of 256 ch) + silu gate ----------------
__global__ void __launch_bounds__(256) gn_gate_kernel(const float* __restrict__ y,
                                                      const float* __restrict__ gt,
                                                      const float* __restrict__ gg,
                                                      const float* __restrict__ gb,
                                                      float* __restrict__ out) {
    int token = blockIdx.x, h = blockIdx.y;
    int c = h * HEADDIM + threadIdx.x;          // 256 threads == HEADDIM
    size_t idx = (size_t)token * HID + c;
    float v = y[idx];
    float s = warp_sum(v);
    float sq = warp_sum(v * v);
    __shared__ float sh0[8], sh1[8];
    int warp = threadIdx.x >> 5, lane = threadIdx.x & 31;
    if (lane == 0) { sh0[warp] = s; sh1[warp] = sq; }
    __syncthreads();
    float S = 0.f, SQ = 0.f;
#pragma unroll
    for (int w = 0; w < 8; w++) { S += sh0[w]; SQ += sh1[w]; }
    float mu  = S * (1.f / HEADDIM);
    float var = SQ * (1.f / HEADDIM) - mu * mu;
    float normed = (v - mu) * rsqrtf(var + LNEPS) * gg[c] + gb[c];
    float g = gt[idx];
    float silu = g / (1.f + expf(-g));
    out[idx] = silu * normed;
}

// ---------------- tf32x3 tensor-core batched GEMM, 3-stage cp.async pipeline ----------------
// C[M,N] = A[M,K] @ B   (B row-major [K,N]; if TRANSB, B is [N,K] row-major -> B^T used)
// Block 128x128, BK=16, 256 threads = 8 warps; warp tile 32(M) x 64(N); mma m16n8k8 tf32.
// Raw f32 staged in DYNAMIC smem (61440 B: 3 stages x 2 operands x 10240 B);
// tf32 hi/lo split happens at fragment-load time.
// 3-buffer ring; tile t+2 load issued BEFORE compute(t) -> 2 tiles of latency in flight.
// EPI: 0 none; 1 decay-mask (retention scores; skips strictly-upper blocks entirely);
//      2 bias+gelu(tanh); 3 bias+residual; 4 residual.
// TRIMK: causal K-trim for the S@V GEMM (reduction stops at m < rowBase+128) and
//        heavy-first y-reversal so long blocks launch in the first wave (LPT).
// SELZ:  blockIdx.z selects B/C from by-value pointer bundles (fused projections).
template <int EPI, bool TRANSB, bool TRIMK, bool SELZ>
__global__ void __launch_bounds__(256) gemm_kernel(
    const float* __restrict__ A, const float* __restrict__ B, float* __restrict__ C,
    int K, int lda, int ldb, int ldc,
    long long sAb, long long sAh, long long sBb, long long sBh,
    long long sCb, long long sCh,
    const float* __restrict__ bias, const float* __restrict__ resid,
    Ptr4 b4, OPtr4 c4) {

    constexpr int STG = GEMM_STG;   // per-stage float count (both layouts fit: 16*136=2176 < 2560)
    // As: [3][128][20] raw f32 (stride 20 floats = 80B, 16B-aligned rows, conflict-free frags)
    // B non-trans: [3][16][136]  ([k][n], stride 136 -> conflict-free frags)
    // B trans:     [3][128][20]  ([n][k], like A)
    extern __shared__ __align__(16) float dynsmem[];
    float* As_ = dynsmem;
    float* Bs_ = dynsmem + 3 * STG;

    // TRIMK: reverse y so the longest-K blocks start in wave 1 (LPT scheduling).
    int rowBase = (TRIMK ? (gridDim.y - 1 - blockIdx.y) : blockIdx.y) * 128;
    int colBase = blockIdx.x * 128;

    // Retention scores: block strictly above the diagonal is all-zero and is
    // never read by the (TRIMK) S@V consumer -> skip entirely.
    if (EPI == 1 && colBase > rowBase) return;

    int bz = blockIdx.z;
    int bb = bz / NHEADS, hh = bz % NHEADS;
    const float* Ab;
    const float* Bb;
    float*       Cb;
    if (SELZ) {
        Ab = A;
        Bb = b4.p[bz];
        Cb = c4.p[bz];
    } else {
        Ab = A + (size_t)bb * sAb + (size_t)hh * sAh;
        Bb = B + (size_t)bb * sBb + (size_t)hh * sBh;
        Cb = C + (size_t)bb * sCb + (size_t)hh * sCh;
    }

    int tid  = threadIdx.x;
    int lane = tid & 31;
    int warp = tid >> 5;
    int g    = lane >> 2;    // groupID 0..7
    int tig  = lane & 3;     // thread-in-group 0..3
    int wm   = warp >> 1;    // 0..3, 32 rows each
    int wn   = warp & 1;     // 0..1, 64 cols each

    float acc[2][8][4];
#pragma unroll
    for (int mt = 0; mt < 2; mt++)
#pragma unroll
        for (int nt = 0; nt < 8; nt++)
#pragma unroll
            for (int r = 0; r < 4; r++) acc[mt][nt][r] = 0.f;

    int Keff = TRIMK ? min(K, rowBase + 128) : K;
    const int T = Keff / 16;

    // ---- tile loader: 16B cp.async chunks ----
    auto load_tile = [&](int t, int buf) {
        int k0 = t * 16;
        float* Ad = As_ + buf * STG;
#pragma unroll
        for (int i = 0; i < 2; i++) {
            int chunk = tid + i * 256;           // 512 chunks: 128 rows x 4
            int m = chunk >> 2, c4i = (chunk & 3) * 4;
            cp16(Ad + m * 20 + c4i, Ab + (size_t)(rowBase + m) * lda + (k0 + c4i));
        }
        float* Bd = Bs_ + buf * STG;
        if (TRANSB) {
#pragma unroll
            for (int i = 0; i < 2; i++) {
                int chunk = tid + i * 256;       // 128 n-rows x 4
                int n = chunk >> 2, c4i = (chunk & 3) * 4;
                cp16(Bd + n * 20 + c4i, Bb + (size_t)(colBase + n) * ldb + (k0 + c4i));
            }
        } else {
#pragma unroll
            for (int i = 0; i < 2; i++) {
                int chunk = tid + i * 256;       // 16 k-rows x 32
                int kk = chunk >> 5, c4i = (chunk & 31) * 4;
                cp16(Bd + kk * 136 + c4i, Bb + (size_t)(k0 + kk) * ldb + (colBase + c4i));
            }
        }
    };

    load_tile(0, 0); cp_commit();
    if (T > 1) { load_tile(1, 1); cp_commit(); }

    int buf = 0;
    for (int t = 0; t < T; t++) {
        if (t < T - 1) cp_wait1(); else cp_wait0();
        __syncthreads();

        // Issue the next prefetch BEFORE compute: its destination buffer was
        // vacated by compute(t-1), which completed before the sync above.
        if (t + 2 < T) { load_tile(t + 2, (buf + 2) % 3); cp_commit(); }

        const float* Av  = As_ + buf * STG;
        const float* Bv  = Bs_ + buf * STG;

#pragma unroll
        for (int ks = 0; ks < 2; ks++) {
            int kk0 = ks * 8;
            // A fragments: raw load + split
            uint32_t ah[2][4], al[2][4];
#pragma unroll
            for (int mt = 0; mt < 2; mt++) {
                int mrow = wm * 32 + mt * 16;
                float r0 = Av[(mrow + g    ) * 20 + kk0 + tig    ];
                float r1 = Av[(mrow + g + 8) * 20 + kk0 + tig    ];
                float r2 = Av[(mrow + g    ) * 20 + kk0 + tig + 4];
                float r3 = Av[(mrow + g + 8) * 20 + kk0 + tig + 4];
                split_tf32(r0, ah[mt][0], al[mt][0]);
                split_tf32(r1, ah[mt][1], al[mt][1]);
                split_tf32(r2, ah[mt][2], al[mt][2]);
                split_tf32(r3, ah[mt][3], al[mt][3]);
            }
            // B fragments: raw load + split
            uint32_t bh[8][2], bl[8][2];
#pragma unroll
            for (int nt = 0; nt < 8; nt++) {
                int n = wn * 64 + nt * 8 + g;
                float q0, q1;
                if (TRANSB) {
                    q0 = Bv[n * 20 + kk0 + tig    ];
                    q1 = Bv[n * 20 + kk0 + tig + 4];
                } else {
                    q0 = Bv[(kk0 + tig    ) * 136 + n];
                    q1 = Bv[(kk0 + tig + 4) * 136 + n];
                }
                split_tf32(q0, bh[nt][0], bl[nt][0]);
                split_tf32(q1, bh[nt][1], bl[nt][1]);
            }
            // tf32x3 mma
#pragma unroll
            for (int mt = 0; mt < 2; mt++) {
#pragma unroll
                for (int nt = 0; nt < 8; nt++) {
                    mma_tf32(acc[mt][nt], ah[mt], bh[nt]);
                    mma_tf32(acc[mt][nt], ah[mt], bl[nt]);
                    mma_tf32(acc[mt][nt], al[mt], bh[nt]);
                }
            }
        }
        __syncthreads();
        buf = (buf + 1) % 3;
    }

    float logg = 0.f;
    if (EPI == 1) {
        // gamma_h = 1 - exp(linspace(ln(1/32), ln(1/512), 8))[h], computed in double
        double lo = -3.4657359027997265;   // ln(1/32)
        double hi = -6.2383246250395077;   // ln(1/512)
        double gamma = 1.0 - exp(lo + (double)hh * ((hi - lo) / 7.0));
        logg = logf((float)gamma);
    }

    // Epilogue: rg pairs (0,1) and (2,3) are adjacent columns -> float2 stores.
#pragma unroll
    for (int mt = 0; mt < 2; mt++) {
#pragma unroll
        for (int nt = 0; nt < 8; nt++) {
#pragma unroll
            for (int half = 0; half < 2; half++) {          // half 0: rg 0,1 ; half 1: rg 2,3
                int r = rowBase + wm * 32 + mt * 16 + g + half * 8;
                int c = colBase + wn * 64 + nt * 8 + 2 * tig;
                float v0 = acc[mt][nt][half * 2 + 0];
                float v1 = acc[mt][nt][half * 2 + 1];
                if (EPI == 1) {
                    int d0 = r - c, d1 = r - (c + 1);       // n - m
                    v0 = (d0 < 0) ? 0.f : v0 * expf((float)d0 * logg);
                    v1 = (d1 < 0) ? 0.f : v1 * expf((float)d1 * logg);
                } else if (EPI == 2) {
                    v0 += bias[c];
                    v1 += bias[c + 1];
                    float t0 = tanhf(0.7978845608028654f * (v0 + 0.044715f * v0 * v0 * v0));
                    float t1 = tanhf(0.7978845608028654f * (v1 + 0.044715f * v1 * v1 * v1));
                    v0 = 0.5f * v0 * (1.f + t0);
                    v1 = 0.5f * v1 * (1.f + t1);
                } else if (EPI == 3) {
                    float2 rr = *(const float2*)&resid[(size_t)r * ldc + c];
                    v0 += bias[c]     + rr.x;
                    v1 += bias[c + 1] + rr.y;
                } else if (EPI == 4) {
                    float2 rr = *(const float2*)&resid[(size_t)r * ldc + c];
                    v0 += rr.x;
                    v1 += rr.y;
                }
                *(float2*)&Cb[(size_t)r * ldc + c] = make_float2(v0, v1);
            }
        }
    }
}

// ---------------- host orchestration ----------------
extern "C" void kernel_launch(void* const* d_in, const int* in_sizes, int n_in,
                              void* d_out, int out_size) {
    (void)in_sizes; (void)n_in; (void)out_size;
    const float* x   = (const float*)d_in[0];
    const float* Wq  = (const float*)d_in[1];
    const float* Wk  = (const float*)d_in[2];
    const float* Wv  = (const float*)d_in[3];
    const float* Wg  = (const float*)d_in[4];
    const float* Wo  = (const float*)d_in[5];
    const float* gng = (const float*)d_in[6];
    const float* gnb = (const float*)d_in[7];
    const float* W1  = (const float*)d_in[8];
    const float* b1  = (const float*)d_in[9];
    const float* W2  = (const float*)d_in[10];
    const float* b2  = (const float*)d_in[11];
    const float* lng = (const float*)d_in[12];
    const float* lnb = (const float*)d_in[13];

    // Raise dynamic-smem cap for every gemm instantiation (sticky; not an alloc;
    // safe to repeat each call — executes immediately even under graph capture).
    cudaFuncSetAttribute(gemm_kernel<0, false, false, true>,  cudaFuncAttributeMaxDynamicSharedMemorySize, GEMM_SMEM_BYTES);
    cudaFuncSetAttribute(gemm_kernel<1, true,  false, false>, cudaFuncAttributeMaxDynamicSharedMemorySize, GEMM_SMEM_BYTES);
    cudaFuncSetAttribute(gemm_kernel<0, false, true,  false>, cudaFuncAttributeMaxDynamicSharedMemorySize, GEMM_SMEM_BYTES);
    cudaFuncSetAttribute(gemm_kernel<4, false, false, false>, cudaFuncAttributeMaxDynamicSharedMemorySize, GEMM_SMEM_BYTES);
    cudaFuncSetAttribute(gemm_kernel<2, false, false, false>, cudaFuncAttributeMaxDynamicSharedMemorySize, GEMM_SMEM_BYTES);
    cudaFuncSetAttribute(gemm_kernel<3, false, false, false>, cudaFuncAttributeMaxDynamicSharedMemorySize, GEMM_SMEM_BYTES);

    float *xb, *xn, *q, *k, *v, *gt, *y, *ret, *rn, *scores, *mid;
    cudaGetSymbolAddress((void**)&xb,  g_x);
    cudaGetSymbolAddress((void**)&xn,  g_xn);
    cudaGetSymbolAddress((void**)&q,   g_q);
    cudaGetSymbolAddress((void**)&k,   g_k);
    cudaGetSymbolAddress((void**)&v,   g_v);
    cudaGetSymbolAddress((void**)&gt,  g_g);
    cudaGetSymbolAddress((void**)&y,   g_y);
    cudaGetSymbolAddress((void**)&ret, g_ret);
    cudaGetSymbolAddress((void**)&rn,  g_rn);
    cudaGetSymbolAddress((void**)&scores, g_scores);
    cudaGetSymbolAddress((void**)&mid, g_mid);

    Ptr4  dummyB = {};
    OPtr4 dummyC = {};

    cudaMemcpyAsync(xb, x, sizeof(float) * (size_t)NTOK * HID, cudaMemcpyDeviceToDevice);

    for (int i = 0; i < NLAYERS; i++) {
        const float* Wqi = Wq + (size_t)i * HID * HID;
        const float* Wki = Wk + (size_t)i * HID * HID;
        const float* Wvi = Wv + (size_t)i * HID * HID;
        const float* Wgi = Wg + (size_t)i * HID * HID;
        const float* Woi = Wo + (size_t)i * HID * HID;
        const float* W1i = W1 + (size_t)i * HID * FFDIM;
        const float* W2i = W2 + (size_t)i * FFDIM * HID;
        const float* b1i = b1 + (size_t)i * FFDIM;
        const float* b2i = b2 + (size_t)i * HID;
        const float* gngi = gng + (size_t)i * HID;
        const float* gnbi = gnb + (size_t)i * HID;

        // xn = LN(x)
        ln_kernel<<<NTOK, 256>>>(xb, lng, lnb, xn);

        // q,k,v,g projections fused into ONE launch (z selects weight/output):
        // 4x512 = 2048 CTAs -> wave tail ~1% instead of ~15% x4.
        {
            dim3 grid(HID / 128, NTOK / 128, 4);
            Ptr4  wb = {{Wqi, Wki, Wvi, Wgi}};
            OPtr4 cb = {{q, k, v, gt}};
            gemm_kernel<0, false, false, true><<<grid, 256, GEMM_SMEM_BYTES>>>(
                xn, nullptr, nullptr, HID, HID, HID, HID,
                0,0,0,0,0,0, nullptr, nullptr, wb, cb);
        }

        // scores[b,h,n,m] = (q_n . k_m) * D[h,n,m]   (batched, B^T, decay epilogue,
        // strictly-upper 128x128 blocks skipped -- never read downstream)
        {
            dim3 grid(SEQ / 128, SEQ / 128, NBATCH * NHEADS);
            gemm_kernel<1, true, false, false><<<grid, 256, GEMM_SMEM_BYTES>>>(
                q, k, scores, HEADDIM, HID, HID, SEQ,
                (long long)SEQ * HID, (long long)HEADDIM,
                (long long)SEQ * HID, (long long)HEADDIM,
                (long long)NHEADS * SEQ * SEQ, (long long)SEQ * SEQ,
                nullptr, nullptr, dummyB, dummyC);
        }

        // y[b,n,h,:] = scores @ v   (batched, causal K-trim, heavy-rows-first order)
        {
            dim3 grid(HEADDIM / 128, SEQ / 128, NBATCH * NHEADS);
            gemm_kernel<0, false, true, false><<<grid, 256, GEMM_SMEM_BYTES>>>(
                scores, v, y, SEQ, SEQ, HID, HID,
                (long long)NHEADS * SEQ * SEQ, (long long)SEQ * SEQ,
                (long long)SEQ * HID, (long long)HEADDIM,
                (long long)SEQ * HID, (long long)HEADDIM,
                nullptr, nullptr, dummyB, dummyC);
        }

        // y = silu(g) * GroupNorm(y)
        gn_gate_kernel<<<dim3(NTOK, NHEADS), 256>>>(y, gt, gngi, gnbi, y);

        // ret = y @ Wo + x
        {
            dim3 grid(HID / 128, NTOK / 128, 1);
            gemm_kernel<4, false, false, false><<<grid, 256, GEMM_SMEM_BYTES>>>(
                y, Woi, ret, HID, HID, HID, HID,
                0,0,0,0,0,0, nullptr, xb, dummyB, dummyC);
        }

        // rn = LN(ret)
        ln_kernel<<<NTOK, 256>>>(ret, lng, lnb, rn);

        // mid = gelu(rn @ W1 + b1)
        {
            dim3 grid(FFDIM / 128, NTOK / 128, 1);
            gemm_kernel<2, false, false, false><<<grid, 256, GEMM_SMEM_BYTES>>>(
                rn, W1i, mid, HID, HID, FFDIM, FFDIM,
                0,0,0,0,0,0, b1i, nullptr, dummyB, dummyC);
        }

        // x = mid @ W2 + b2 + ret
        {
            dim3 grid(HID / 128, NTOK / 128, 1);
            gemm_kernel<3, false, false, false><<<grid, 256, GEMM_SMEM_BYTES>>>(
                mid, W2i, xb, FFDIM, FFDIM, HID, HID,
                0,0,0,0,0,0, b2i, ret, dummyB, dummyC);
        }
    }

    cudaMemcpyAsync(d_out, xb, sizeof(float) * (size_t)NTOK * HID, cudaMemcpyDeviceToDevice);
}

// round 9
// speedup vs baseline: 1.7400x; 1.7400x over previous
#include <cuda_runtime.h>
#include <cuda_bf16.h>
#include <math.h>
#include <stdint.h>

#define NLAYERS 2
#define HID 2048
#define NHEADS 8
#define HEADDIM 256
#define FFDIM 8192
#define NBATCH 4
#define SEQ 1024
#define NTOK (NBATCH * SEQ)   // 4096
#define LNEPS 1e-5f

// ---------------- scratch (static device globals; no allocation at runtime) ----------------
__device__ float g_x  [NTOK * HID];
__device__ float g_xn [NTOK * HID];
__device__ float g_q  [NTOK * HID];
__device__ float g_k  [NTOK * HID];
__device__ float g_v  [NTOK * HID];
__device__ float g_g  [NTOK * HID];
__device__ float g_y  [NTOK * HID];
__device__ float g_ret[NTOK * HID];
__device__ float g_rn [NTOK * HID];
__device__ float g_scores[(size_t)NBATCH * NHEADS * SEQ * SEQ];  // 134 MB
__device__ float g_mid[(size_t)NTOK * FFDIM];                    // 134 MB

// by-value pointer bundles for the fused 4-projection launch
struct Ptr4  { const float* p[4]; };
struct OPtr4 { float*       p[4]; };

// smem geometry (words = uint32 = packed bf16x2)
#define AW 12                      // A plane row stride in words (bank-conflict-free: 12g+tig perm)
#define A_PLANE (128 * AW)         // 1536 words per plane
#define BW 136                     // B plane row stride in words (8*tig+g perm)
#define B_PLANE (8 * BW)           // 1088 words per plane
#define STAGE (2 * A_PLANE + 2 * B_PLANE)   // 5248 words
#define GEMM_SMEM_BYTES (2 * STAGE * 4)     // 41984 B

// ---------------- helpers ----------------
__device__ __forceinline__ float warp_sum(float v) {
#pragma unroll
    for (int o = 16; o > 0; o >>= 1) v += __shfl_down_sync(0xffffffffu, v, o);
    return v;
}

// split (x0,x1) -> packed bf16x2 hi word + lo word (low half = x0 = lower-k element)
__device__ __forceinline__ void split2(float x0, float x1, uint32_t& hi, uint32_t& lo) {
    __nv_bfloat162 h = __float22bfloat162_rn(make_float2(x0, x1));
    float h0 = __bfloat162float(h.x);
    float h1 = __bfloat162float(h.y);
    __nv_bfloat162 l = __float22bfloat162_rn(make_float2(x0 - h0, x1 - h1));
    hi = *(uint32_t*)&h;
    lo = *(uint32_t*)&l;
}

__device__ __forceinline__ void mma_bf16(float* c, const uint32_t* a, const uint32_t* b) {
    asm volatile(
        "mma.sync.aligned.m16n8k16.row.col.f32.bf16.bf16.f32 "
        "{%0,%1,%2,%3}, {%4,%5,%6,%7}, {%8,%9}, {%0,%1,%2,%3};"
        : "+f"(c[0]), "+f"(c[1]), "+f"(c[2]), "+f"(c[3])
        : "r"(a[0]), "r"(a[1]), "r"(a[2]), "r"(a[3]), "r"(b[0]), "r"(b[1]));
}

// ---------------- LayerNorm over HID channels, one block per token ----------------
__global__ void __launch_bounds__(256) ln_kernel(const float* __restrict__ x,
                                                 const float* __restrict__ gamma,
                                                 const float* __restrict__ beta,
                                                 float* __restrict__ out) {
    int row = blockIdx.x;
    const float* xr = x + (size_t)row * HID;
    float lv[8];
    float s = 0.f, sq = 0.f;
#pragma unroll
    for (int i = 0; i < 8; i++) {
        float v = xr[threadIdx.x + i * 256];
        lv[i] = v; s += v; sq += v * v;
    }
    s = warp_sum(s); sq = warp_sum(sq);
    __shared__ float sh0[8], sh1[8];
    int warp = threadIdx.x >> 5, lane = threadIdx.x & 31;
    if (lane == 0) { sh0[warp] = s; sh1[warp] = sq; }
    __syncthreads();
    float S = 0.f, SQ = 0.f;
#pragma unroll
    for (int w = 0; w < 8; w++) { S += sh0[w]; SQ += sh1[w]; }
    float mu  = S * (1.f / HID);
    float var = SQ * (1.f / HID) - mu * mu;
    float inv = rsqrtf(var + LNEPS);
    float* orow = out + (size_t)row * HID;
#pragma unroll
    for (int i = 0; i < 8; i++) {
        int c = threadIdx.x + i * 256;
        orow[c] = (lv[i] - mu) * inv * gamma[c] + beta[c];
    }
}

// ---------------- GroupNorm (per token, per head of 256 ch) + silu gate ----------------
__global__ void __launch_bounds__(256) gn_gate_kernel(const float* __restrict__ y,
                                                      const float* __restrict__ gt,
                                                      const float* __restrict__ gg,
                                                      const float* __restrict__ gb,
                                                      float* __restrict__ out) {
    int token = blockIdx.x, h = blockIdx.y;
    int c = h * HEADDIM + threadIdx.x;          // 256 threads == HEADDIM
    size_t idx = (size_t)token * HID + c;
    float v = y[idx];
    float s = warp_sum(v);
    float sq = warp_sum(v * v);
    __shared__ float sh0[8], sh1[8];
    int warp = threadIdx.x >> 5, lane = threadIdx.x & 31;
    if (lane == 0) { sh0[warp] = s; sh1[warp] = sq; }
    __syncthreads();
    float S = 0.f, SQ = 0.f;
#pragma unroll
    for (int w = 0; w < 8; w++) { S += sh0[w]; SQ += sh1[w]; }
    float mu  = S * (1.f / HEADDIM);
    float var = SQ * (1.f / HEADDIM) - mu * mu;
    float normed = (v - mu) * rsqrtf(var + LNEPS) * gg[c] + gb[c];
    float g = gt[idx];
    float silu = g / (1.f + expf(-g));
    out[idx] = silu * normed;
}

// ---------------- bf16x3 tensor-core batched GEMM ----------------
// C[M,N] = A[M,K] @ B   (B row-major [K,N]; if TRANSB, B is [N,K] row-major -> B^T used)
// Block 128x128, BK=16, 256 threads = 8 warps; warp tile 32(M) x 64(N); mma m16n8k16 bf16.
// Fill path: LDG f32 -> regs -> split to bf16 hi/lo packed planes -> STS (split done ONCE).
// Consumer path: pure LDS of packed fragments + 3 mma per acc tile (ah*bh + ah*bl + al*bh).
// Double-buffered smem; LDG for tile t+1 in flight during compute(t).
// EPI: 0 none; 1 decay-mask; 2 bias+gelu(tanh); 3 bias+residual; 4 residual.
// TRIMK: causal K-trim (m < rowBase+128) + heavy-first y-reversal (LPT).
// SELZ:  blockIdx.z selects B/C from by-value pointer bundles (fused projections).
template <int EPI, bool TRANSB, bool TRIMK, bool SELZ>
__global__ void __launch_bounds__(256, 2) gemm_kernel(
    const float* __restrict__ A, const float* __restrict__ B, float* __restrict__ C,
    int K, int lda, int ldb, int ldc,
    long long sAb, long long sAh, long long sBb, long long sBh,
    long long sCb, long long sCh,
    const float* __restrict__ bias, const float* __restrict__ resid,
    Ptr4 b4, OPtr4 c4) {

    extern __shared__ __align__(16) uint32_t dynsmem[];

    // TRIMK: reverse y so the longest-K blocks start in wave 1 (LPT scheduling).
    int rowBase = (TRIMK ? (gridDim.y - 1 - blockIdx.y) : blockIdx.y) * 128;
    int colBase = blockIdx.x * 128;

    // Retention scores: block strictly above the diagonal is all-zero and is
    // never read by the (TRIMK) S@V consumer -> skip entirely.
    if (EPI == 1 && colBase > rowBase) return;

    int bz = blockIdx.z;
    int bb = bz / NHEADS, hh = bz % NHEADS;
    const float* Ab;
    const float* Bb;
    float*       Cb;
    if (SELZ) {
        Ab = A; Bb = b4.p[bz]; Cb = c4.p[bz];
    } else {
        Ab = A + (size_t)bb * sAb + (size_t)hh * sAh;
        Bb = B + (size_t)bb * sBb + (size_t)hh * sBh;
        Cb = C + (size_t)bb * sCb + (size_t)hh * sCh;
    }

    int tid  = threadIdx.x;
    int lane = tid & 31;
    int warp = tid >> 5;
    int g    = lane >> 2;    // groupID 0..7
    int tig  = lane & 3;     // thread-in-group 0..3
    int wm   = warp >> 1;    // 0..3, 32 rows each
    int wn   = warp & 1;     // 0..1, 64 cols each

    float acc[2][8][4];
#pragma unroll
    for (int mt = 0; mt < 2; mt++)
#pragma unroll
        for (int nt = 0; nt < 8; nt++)
#pragma unroll
            for (int r = 0; r < 4; r++) acc[mt][nt][r] = 0.f;

    int Keff = TRIMK ? min(K, rowBase + 128) : K;
    const int T = Keff / 16;

    float Ra[8], Rb[8];     // register staging for the next tile

    // ---- gmem -> regs ----
    auto ldg_tile = [&](int t) {
        int k0 = t * 16;
        {   // A: thread -> row tid/2, k-half tid&1 (8 consecutive k)
            int m = tid >> 1, kh = tid & 1;
            const float* ap = Ab + (size_t)(rowBase + m) * lda + k0 + kh * 8;
            *(float4*)&Ra[0] = *(const float4*)ap;
            *(float4*)&Ra[4] = *(const float4*)(ap + 4);
        }
        if (TRANSB) {       // B[n][k]: thread -> n tid&127, k-half tid>>7
            int n = tid & 127, kh = tid >> 7;
            const float* bp = Bb + (size_t)(colBase + n) * ldb + k0 + kh * 8;
            *(float4*)&Rb[0] = *(const float4*)bp;
            *(float4*)&Rb[4] = *(const float4*)(bp + 4);
        } else {            // B[k][n]: thread -> kpair tid>>5, 4 consecutive n
            int kp = tid >> 5, n4 = (tid & 31) * 4;
            const float* bp = Bb + (size_t)(k0 + 2 * kp) * ldb + colBase + n4;
            *(float4*)&Rb[0] = *(const float4*)bp;          // k even
            *(float4*)&Rb[4] = *(const float4*)(bp + ldb);  // k odd
        }
    };

    // ---- regs -> split -> smem planes ----
    auto sts_tile = [&](int buf) {
        uint32_t* Sa_hi = dynsmem + buf * STAGE;
        uint32_t* Sa_lo = Sa_hi + A_PLANE;
        uint32_t* Sb_hi = Sa_hi + 2 * A_PLANE;
        uint32_t* Sb_lo = Sb_hi + B_PLANE;
        {   // A: 4 packed words per plane, STS.128
            int m = tid >> 1, kh = tid & 1;
            uint32_t h[4], l[4];
#pragma unroll
            for (int i = 0; i < 4; i++) split2(Ra[2 * i], Ra[2 * i + 1], h[i], l[i]);
            int aw = m * AW + kh * 4;
            *(uint4*)&Sa_hi[aw] = make_uint4(h[0], h[1], h[2], h[3]);
            *(uint4*)&Sa_lo[aw] = make_uint4(l[0], l[1], l[2], l[3]);
        }
        if (TRANSB) {       // pairs along k within the thread's 8 floats
            int n = tid & 127, kh = tid >> 7;
#pragma unroll
            for (int i = 0; i < 4; i++) {
                uint32_t h, l;
                split2(Rb[2 * i], Rb[2 * i + 1], h, l);
                int w = (kh * 4 + i) * BW + n;
                Sb_hi[w] = h; Sb_lo[w] = l;
            }
        } else {            // pairs across the two k-rows
            int kp = tid >> 5, n4 = (tid & 31) * 4;
            uint32_t h[4], l[4];
#pragma unroll
            for (int i = 0; i < 4; i++) split2(Rb[i], Rb[4 + i], h[i], l[i]);
            int w = kp * BW + n4;
            *(uint4*)&Sb_hi[w] = make_uint4(h[0], h[1], h[2], h[3]);
            *(uint4*)&Sb_lo[w] = make_uint4(l[0], l[1], l[2], l[3]);
        }
    };

    // ---- pipeline ----
    ldg_tile(0);
    sts_tile(0);
    if (T > 1) ldg_tile(1);
    __syncthreads();

    for (int t = 0; t < T; t++) {
        const uint32_t* Sa_hi = dynsmem + (t & 1) * STAGE;
        const uint32_t* Sa_lo = Sa_hi + A_PLANE;
        const uint32_t* Sb_hi = Sa_hi + 2 * A_PLANE;
        const uint32_t* Sb_lo = Sb_hi + B_PLANE;

        // A fragments (hi+lo), 16 regs
        uint32_t ah[2][4], al[2][4];
#pragma unroll
        for (int mt = 0; mt < 2; mt++) {
            int r0 = (wm * 32 + mt * 16 + g) * AW;
            int r1 = r0 + 8 * AW;
            ah[mt][0] = Sa_hi[r0 + tig];     ah[mt][1] = Sa_hi[r1 + tig];
            ah[mt][2] = Sa_hi[r0 + tig + 4]; ah[mt][3] = Sa_hi[r1 + tig + 4];
            al[mt][0] = Sa_lo[r0 + tig];     al[mt][1] = Sa_lo[r1 + tig];
            al[mt][2] = Sa_lo[r0 + tig + 4]; al[mt][3] = Sa_lo[r1 + tig + 4];
        }
        // B fragments loaded per nt (short live range), 3 mma per acc tile
#pragma unroll
        for (int nt = 0; nt < 8; nt++) {
            int n = wn * 64 + nt * 8 + g;
            uint32_t bh[2], bl[2];
            bh[0] = Sb_hi[tig * BW + n];  bh[1] = Sb_hi[(tig + 4) * BW + n];
            bl[0] = Sb_lo[tig * BW + n];  bl[1] = Sb_lo[(tig + 4) * BW + n];
#pragma unroll
            for (int mt = 0; mt < 2; mt++) {
                mma_bf16(acc[mt][nt], ah[mt], bh);
                mma_bf16(acc[mt][nt], ah[mt], bl);
                mma_bf16(acc[mt][nt], al[mt], bh);
            }
        }

        if (t + 1 < T) {
            __syncthreads();                 // everyone done reading buf[(t+1)&1] (iter t-1)
            sts_tile((t + 1) & 1);           // consumes regs from ldg_tile(t+1)
            if (t + 2 < T) ldg_tile(t + 2);  // issue next loads; covered by compute(t+1)
            __syncthreads();                 // STS visible before compute(t+1)
        }
    }

    float logg = 0.f;
    if (EPI == 1) {
        // gamma_h = 1 - exp(linspace(ln(1/32), ln(1/512), 8))[h], computed in double
        double lo = -3.4657359027997265;   // ln(1/32)
        double hi = -6.2383246250395077;   // ln(1/512)
        double gamma = 1.0 - exp(lo + (double)hh * ((hi - lo) / 7.0));
        logg = logf((float)gamma);
    }

    // Epilogue: rg pairs (0,1) and (2,3) are adjacent columns -> float2 stores.
#pragma unroll
    for (int mt = 0; mt < 2; mt++) {
#pragma unroll
        for (int nt = 0; nt < 8; nt++) {
#pragma unroll
            for (int half = 0; half < 2; half++) {          // half 0: rg 0,1 ; half 1: rg 2,3
                int r = rowBase + wm * 32 + mt * 16 + g + half * 8;
                int c = colBase + wn * 64 + nt * 8 + 2 * tig;
                float v0 = acc[mt][nt][half * 2 + 0];
                float v1 = acc[mt][nt][half * 2 + 1];
                if (EPI == 1) {
                    int d0 = r - c, d1 = r - (c + 1);       // n - m
                    v0 = (d0 < 0) ? 0.f : v0 * expf((float)d0 * logg);
                    v1 = (d1 < 0) ? 0.f : v1 * expf((float)d1 * logg);
                } else if (EPI == 2) {
                    v0 += bias[c];
                    v1 += bias[c + 1];
                    float t0 = tanhf(0.7978845608028654f * (v0 + 0.044715f * v0 * v0 * v0));
                    float t1 = tanhf(0.7978845608028654f * (v1 + 0.044715f * v1 * v1 * v1));
                    v0 = 0.5f * v0 * (1.f + t0);
                    v1 = 0.5f * v1 * (1.f + t1);
                } else if (EPI == 3) {
                    float2 rr = *(const float2*)&resid[(size_t)r * ldc + c];
                    v0 += bias[c]     + rr.x;
                    v1 += bias[c + 1] + rr.y;
                } else if (EPI == 4) {
                    float2 rr = *(const float2*)&resid[(size_t)r * ldc + c];
                    v0 += rr.x;
                    v1 += rr.y;
                }
                *(float2*)&Cb[(size_t)r * ldc + c] = make_float2(v0, v1);
            }
        }
    }
}

// ---------------- host orchestration ----------------
extern "C" void kernel_launch(void* const* d_in, const int* in_sizes, int n_in,
                              void* d_out, int out_size) {
    (void)in_sizes; (void)n_in; (void)out_size;
    const float* x   = (const float*)d_in[0];
    const float* Wq  = (const float*)d_in[1];
    const float* Wk  = (const float*)d_in[2];
    const float* Wv  = (const float*)d_in[3];
    const float* Wg  = (const float*)d_in[4];
    const float* Wo  = (const float*)d_in[5];
    const float* gng = (const float*)d_in[6];
    const float* gnb = (const float*)d_in[7];
    const float* W1  = (const float*)d_in[8];
    const float* b1  = (const float*)d_in[9];
    const float* W2  = (const float*)d_in[10];
    const float* b2  = (const float*)d_in[11];
    const float* lng = (const float*)d_in[12];
    const float* lnb = (const float*)d_in[13];

    // Dynamic-smem cap (41984 B is under the 48KB default, but keep sticky attr for safety).
    cudaFuncSetAttribute(gemm_kernel<0, false, false, true>,  cudaFuncAttributeMaxDynamicSharedMemorySize, GEMM_SMEM_BYTES);
    cudaFuncSetAttribute(gemm_kernel<1, true,  false, false>, cudaFuncAttributeMaxDynamicSharedMemorySize, GEMM_SMEM_BYTES);
    cudaFuncSetAttribute(gemm_kernel<0, false, true,  false>, cudaFuncAttributeMaxDynamicSharedMemorySize, GEMM_SMEM_BYTES);
    cudaFuncSetAttribute(gemm_kernel<4, false, false, false>, cudaFuncAttributeMaxDynamicSharedMemorySize, GEMM_SMEM_BYTES);
    cudaFuncSetAttribute(gemm_kernel<2, false, false, false>, cudaFuncAttributeMaxDynamicSharedMemorySize, GEMM_SMEM_BYTES);
    cudaFuncSetAttribute(gemm_kernel<3, false, false, false>, cudaFuncAttributeMaxDynamicSharedMemorySize, GEMM_SMEM_BYTES);

    float *xb, *xn, *q, *k, *v, *gt, *y, *ret, *rn, *scores, *mid;
    cudaGetSymbolAddress((void**)&xb,  g_x);
    cudaGetSymbolAddress((void**)&xn,  g_xn);
    cudaGetSymbolAddress((void**)&q,   g_q);
    cudaGetSymbolAddress((void**)&k,   g_k);
    cudaGetSymbolAddress((void**)&v,   g_v);
    cudaGetSymbolAddress((void**)&gt,  g_g);
    cudaGetSymbolAddress((void**)&y,   g_y);
    cudaGetSymbolAddress((void**)&ret, g_ret);
    cudaGetSymbolAddress((void**)&rn,  g_rn);
    cudaGetSymbolAddress((void**)&scores, g_scores);
    cudaGetSymbolAddress((void**)&mid, g_mid);

    Ptr4  dummyB = {};
    OPtr4 dummyC = {};

    cudaMemcpyAsync(xb, x, sizeof(float) * (size_t)NTOK * HID, cudaMemcpyDeviceToDevice);

    for (int i = 0; i < NLAYERS; i++) {
        const float* Wqi = Wq + (size_t)i * HID * HID;
        const float* Wki = Wk + (size_t)i * HID * HID;
        const float* Wvi = Wv + (size_t)i * HID * HID;
        const float* Wgi = Wg + (size_t)i * HID * HID;
        const float* Woi = Wo + (size_t)i * HID * HID;
        const float* W1i = W1 + (size_t)i * HID * FFDIM;
        const float* W2i = W2 + (size_t)i * FFDIM * HID;
        const float* b1i = b1 + (size_t)i * FFDIM;
        const float* b2i = b2 + (size_t)i * HID;
        const float* gngi = gng + (size_t)i * HID;
        const float* gnbi = gnb + (size_t)i * HID;

        // xn = LN(x)
        ln_kernel<<<NTOK, 256>>>(xb, lng, lnb, xn);

        // q,k,v,g projections fused into ONE launch (z selects weight/output)
        {
            dim3 grid(HID / 128, NTOK / 128, 4);
            Ptr4  wb = {{Wqi, Wki, Wvi, Wgi}};
            OPtr4 cb = {{q, k, v, gt}};
            gemm_kernel<0, false, false, true><<<grid, 256, GEMM_SMEM_BYTES>>>(
                xn, nullptr, nullptr, HID, HID, HID, HID,
                0,0,0,0,0,0, nullptr, nullptr, wb, cb);
        }

        // scores[b,h,n,m] = (q_n . k_m) * D[h,n,m]  (B^T, decay epilogue, upper blocks skipped)
        {
            dim3 grid(SEQ / 128, SEQ / 128, NBATCH * NHEADS);
            gemm_kernel<1, true, false, false><<<grid, 256, GEMM_SMEM_BYTES>>>(
                q, k, scores, HEADDIM, HID, HID, SEQ,
                (long long)SEQ * HID, (long long)HEADDIM,
                (long long)SEQ * HID, (long long)HEADDIM,
                (long long)NHEADS * SEQ * SEQ, (long long)SEQ * SEQ,
                nullptr, nullptr, dummyB, dummyC);
        }

        // y[b,n,h,:] = scores @ v   (causal K-trim, heavy-rows-first order)
        {
            dim3 grid(HEADDIM / 128, SEQ / 128, NBATCH * NHEADS);
            gemm_kernel<0, false, true, false><<<grid, 256, GEMM_SMEM_BYTES>>>(
                scores, v, y, SEQ, SEQ, HID, HID,
                (long long)NHEADS * SEQ * SEQ, (long long)SEQ * SEQ,
                (long long)SEQ * HID, (long long)HEADDIM,
                (long long)SEQ * HID, (long long)HEADDIM,
                nullptr, nullptr, dummyB, dummyC);
        }

        // y = silu(g) * GroupNorm(y)
        gn_gate_kernel<<<dim3(NTOK, NHEADS), 256>>>(y, gt, gngi, gnbi, y);

        // ret = y @ Wo + x
        {
            dim3 grid(HID / 128, NTOK / 128, 1);
            gemm_kernel<4, false, false, false><<<grid, 256, GEMM_SMEM_BYTES>>>(
                y, Woi, ret, HID, HID, HID, HID,
                0,0,0,0,0,0, nullptr, xb, dummyB, dummyC);
        }

        // rn = LN(ret)
        ln_kernel<<<NTOK, 256>>>(ret, lng, lnb, rn);

        // mid = gelu(rn @ W1 + b1)
        {
            dim3 grid(FFDIM / 128, NTOK / 128, 1);
            gemm_kernel<2, false, false, false><<<grid, 256, GEMM_SMEM_BYTES>>>(
                rn, W1i, mid, HID, HID, FFDIM, FFDIM,
                0,0,0,0,0,0, b1i, nullptr, dummyB, dummyC);
        }

        // x = mid @ W2 + b2 + ret
        {
            dim3 grid(HID / 128, NTOK / 128, 1);
            gemm_kernel<3, false, false, false><<<grid, 256, GEMM_SMEM_BYTES>>>(
                mid, W2i, xb, FFDIM, FFDIM, HID, HID,
                0,0,0,0,0,0, b2i, ret, dummyB, dummyC);
        }
    }

    cudaMemcpyAsync(d_out, xb, sizeof(float) * (size_t)NTOK * HID, cudaMemcpyDeviceToDevice);
}

// round 15
// speedup vs baseline: 1.8737x; 1.0768x over previous
#include <cuda_runtime.h>
#include <cuda_bf16.h>
#include <math.h>
#include <stdint.h>

#define NLAYERS 2
#define HID 2048
#define NHEADS 8
#define HEADDIM 256
#define FFDIM 8192
#define NBATCH 4
#define SEQ 1024
#define NTOK (NBATCH * SEQ)   // 4096
#define LNEPS 1e-5f

// ---------------- scratch (static device globals; no allocation at runtime) ----------------
__device__ __align__(16) float g_x  [NTOK * HID];
__device__ __align__(16) float g_v  [NTOK * HID];
__device__ __align__(16) float g_g  [NTOK * HID];
__device__ __align__(16) float g_y  [NTOK * HID];
__device__ __align__(16) float g_ret[NTOK * HID];

// bf16 hi/lo plane buffers (uint32 words = packed bf16x2 pairs along the K dim)
__device__ __align__(16) uint32_t g_xnh[NTOK * 1024], g_xnl[NTOK * 1024];
__device__ __align__(16) uint32_t g_qh [NTOK * 1024], g_ql [NTOK * 1024];
__device__ __align__(16) uint32_t g_kh [NTOK * 1024], g_kl [NTOK * 1024];
__device__ __align__(16) uint32_t g_vbh[(NTOK/2) * HID], g_vbl[(NTOK/2) * HID];     // pairs along tokens
__device__ __align__(16) uint32_t g_sh [(size_t)32 * 1024 * 512], g_sl [(size_t)32 * 1024 * 512]; // scores planes
__device__ __align__(16) uint32_t g_yph[NTOK * 1024], g_ypl[NTOK * 1024];           // gated/GN output
__device__ __align__(16) uint32_t g_rnh[NTOK * 1024], g_rnl[NTOK * 1024];
__device__ __align__(16) uint32_t g_mh [(size_t)NTOK * 4096], g_ml [(size_t)NTOK * 4096]; // mid planes

// weight planes, both layers: Wq,Wk,Wv,Wg,Wo (1024x2048 words each), W1 (1024x8192), W2 (4096x2048)
#define WQSZ (1024 * 2048)
#define W1SZ (1024 * 8192)
#define W2SZ (4096 * 2048)
#define WPL  (5 * WQSZ + W1SZ + W2SZ)   // per-layer words
__device__ __align__(16) uint32_t g_wh[(size_t)2 * WPL], g_wl[(size_t)2 * WPL];

struct BSel { const uint32_t* h[4]; const uint32_t* l[4]; };
struct OSel { float* f[4]; uint32_t* h[4]; uint32_t* l[4]; };

// ---------------- helpers ----------------
__device__ __forceinline__ float warp_sum(float v) {
#pragma unroll
    for (int o = 16; o > 0; o >>= 1) v += __shfl_down_sync(0xffffffffu, v, o);
    return v;
}

// split (x0,x1) -> packed bf16x2 hi word + lo word (low half = x0 = lower-k element)
__device__ __forceinline__ void split2(float x0, float x1, uint32_t& hi, uint32_t& lo) {
    __nv_bfloat162 h = __float22bfloat162_rn(make_float2(x0, x1));
    float h0 = __bfloat162float(h.x);
    float h1 = __bfloat162float(h.y);
    __nv_bfloat162 l = __float22bfloat162_rn(make_float2(x0 - h0, x1 - h1));
    hi = *(uint32_t*)&h;
    lo = *(uint32_t*)&l;
}

__device__ __forceinline__ void mma_bf16(float* c, const uint32_t* a, const uint32_t* b) {
    asm volatile(
        "mma.sync.aligned.m16n8k16.row.col.f32.bf16.bf16.f32 "
        "{%0,%1,%2,%3}, {%4,%5,%6,%7}, {%8,%9}, {%0,%1,%2,%3};"
        : "+f"(c[0]), "+f"(c[1]), "+f"(c[2]), "+f"(c[3])
        : "r"(a[0]), "r"(a[1]), "r"(a[2]), "r"(a[3]), "r"(b[0]), "r"(b[1]));
}

__device__ __forceinline__ void cp16(void* smem_dst, const void* gmem_src) {
    uint32_t d = (uint32_t)__cvta_generic_to_shared(smem_dst);
    asm volatile("cp.async.cg.shared.global [%0], [%1], 16;\n" :: "r"(d), "l"(gmem_src));
}
__device__ __forceinline__ void cp_commit() { asm volatile("cp.async.commit_group;\n"); }
__device__ __forceinline__ void cp_wait1()  { asm volatile("cp.async.wait_group 1;\n"); }
__device__ __forceinline__ void cp_wait0()  { asm volatile("cp.async.wait_group 0;\n"); }

// ---------------- generic across-row pair split: planes[kk][n] = split(src[2kk][n], src[2kk+1][n]) ----------------
__global__ void __launch_bounds__(256) wsplit_kernel(const float* __restrict__ src,
                                                     uint32_t* __restrict__ dhi,
                                                     uint32_t* __restrict__ dlo,
                                                     int N, int total) {
    int idx = blockIdx.x * 256 + threadIdx.x;
    if (idx >= total) return;
    int nq = N >> 2;
    long long kk = idx / nq;
    int n4 = (idx - kk * nq) * 4;
    const float* r0 = src + 2 * kk * N + n4;
    float4 a = *(const float4*)r0;
    float4 b = *(const float4*)(r0 + N);
    uint32_t h[4], l[4];
    split2(a.x, b.x, h[0], l[0]);
    split2(a.y, b.y, h[1], l[1]);
    split2(a.z, b.z, h[2], l[2]);
    split2(a.w, b.w, h[3], l[3]);
    long long w = kk * N + n4;
    *(uint4*)&dhi[w] = make_uint4(h[0], h[1], h[2], h[3]);
    *(uint4*)&dlo[w] = make_uint4(l[0], l[1], l[2], l[3]);
}

// ---------------- LayerNorm -> bf16 planes (pairs along channels) ----------------
__global__ void __launch_bounds__(256) ln_split_kernel(const float* __restrict__ x,
                                                       const float* __restrict__ gamma,
                                                       const float* __restrict__ beta,
                                                       uint32_t* __restrict__ oh,
                                                       uint32_t* __restrict__ ol) {
    int row = blockIdx.x;
    int tid = threadIdx.x;
    const float* xr = x + (size_t)row * HID + tid * 8;
    float4 c0 = *(const float4*)xr;
    float4 c1 = *(const float4*)(xr + 4);
    float vv[8] = {c0.x, c0.y, c0.z, c0.w, c1.x, c1.y, c1.z, c1.w};
    float s = 0.f, sq = 0.f;
#pragma unroll
    for (int i = 0; i < 8; i++) { s += vv[i]; sq += vv[i] * vv[i]; }
    s = warp_sum(s); sq = warp_sum(sq);
    __shared__ float sh0[8], sh1[8];
    int warp = tid >> 5, lane = tid & 31;
    if (lane == 0) { sh0[warp] = s; sh1[warp] = sq; }
    __syncthreads();
    float S = 0.f, SQ = 0.f;
#pragma unroll
    for (int w = 0; w < 8; w++) { S += sh0[w]; SQ += sh1[w]; }
    float mu  = S * (1.f / HID);
    float var = SQ * (1.f / HID) - mu * mu;
    float inv = rsqrtf(var + LNEPS);
    float4 g0 = *(const float4*)&gamma[tid * 8];
    float4 g1 = *(const float4*)&gamma[tid * 8 + 4];
    float4 b0 = *(const float4*)&beta[tid * 8];
    float4 b1 = *(const float4*)&beta[tid * 8 + 4];
    float gg[8] = {g0.x, g0.y, g0.z, g0.w, g1.x, g1.y, g1.z, g1.w};
    float bb[8] = {b0.x, b0.y, b0.z, b0.w, b1.x, b1.y, b1.z, b1.w};
    uint32_t h[4], l[4];
#pragma unroll
    for (int j = 0; j < 4; j++) {
        float o0 = (vv[2*j]   - mu) * inv * gg[2*j]   + bb[2*j];
        float o1 = (vv[2*j+1] - mu) * inv * gg[2*j+1] + bb[2*j+1];
        split2(o0, o1, h[j], l[j]);
    }
    size_t w = (size_t)row * 1024 + tid * 4;
    *(uint4*)&oh[w] = make_uint4(h[0], h[1], h[2], h[3]);
    *(uint4*)&ol[w] = make_uint4(l[0], l[1], l[2], l[3]);
}

// ---------------- GroupNorm + silu gate -> bf16 planes ----------------
__global__ void __launch_bounds__(128) gn_gate_split_kernel(const float* __restrict__ y,
                                                            const float* __restrict__ gt,
                                                            const float* __restrict__ gg,
                                                            const float* __restrict__ gb,
                                                            uint32_t* __restrict__ oh,
                                                            uint32_t* __restrict__ ol) {
    int token = blockIdx.x, h = blockIdx.y;
    int tid = threadIdx.x;
    int c = h * HEADDIM + 2 * tid;
    size_t idx = (size_t)token * HID + c;
    float2 v = *(const float2*)&y[idx];
    float s = v.x + v.y, sq = v.x * v.x + v.y * v.y;
    s = warp_sum(s); sq = warp_sum(sq);
    __shared__ float sh0[4], sh1[4];
    int warp = tid >> 5, lane = tid & 31;
    if (lane == 0) { sh0[warp] = s; sh1[warp] = sq; }
    __syncthreads();
    float S = 0.f, SQ = 0.f;
#pragma unroll
    for (int w = 0; w < 4; w++) { S += sh0[w]; SQ += sh1[w]; }
    float mu  = S * (1.f / HEADDIM);
    float var = SQ * (1.f / HEADDIM) - mu * mu;
    float inv = rsqrtf(var + LNEPS);
    float2 gv = *(const float2*)&gt[idx];
    float o0 = ((v.x - mu) * inv * gg[c]     + gb[c])     * (gv.x / (1.f + expf(-gv.x)));
    float o1 = ((v.y - mu) * inv * gg[c + 1] + gb[c + 1]) * (gv.y / (1.f + expf(-gv.y)));
    uint32_t hw, lw;
    split2(o0, o1, hw, lw);
    size_t w = (size_t)token * 1024 + h * 128 + tid;
    oh[w] = hw; ol[w] = lw;
}

// ---------------- pure-bf16 tensor-core batched GEMM, cp.async 3-stage pipeline ----------------
// Operands are pre-split bf16 hi/lo planes (words = bf16x2 pairs along K).
// A planes: [M][K/2] words.  B planes (BNROWS=false): [K/2][N] words;  (BNROWS=true): [N][K/2] words (B^T style).
// Block 128x128, BK=16, 256 threads = 8 warps; warp tile 32(M) x 64(N); mma m16n8k16 bf16 x3 terms.
// EPI: 0 none; 1 decay-mask; 2 bias+gelu(tanh); 3 bias+residual; 4 residual.
// TRIMK: causal K-trim (m < rowBase+128) + heavy-first y-reversal (LPT).
// SELZ:  blockIdx.z selects B/C from bundles (fused QKVG).
// OUTP:  0 = f32 C; 1 = split planes C; 2 = SELZ mix (z<2 planes, else f32).
template <int EPI, bool TRIMK, bool SELZ, int OUTP, bool BNROWS>
__global__ void __launch_bounds__(256, 2) gemm_kernel(
    const uint32_t* __restrict__ Ah, const uint32_t* __restrict__ Al,
    const uint32_t* __restrict__ Bh, const uint32_t* __restrict__ Bl,
    float* Cf, uint32_t* Ch, uint32_t* Cl,
    int K, int ldaw, int ldbw, int ldc, int ldcw,
    long long sAb, long long sAh_, long long sBb, long long sBh_,
    long long sCb, long long sCh_,
    const float* __restrict__ bias, const float* __restrict__ resid,
    BSel bsel, OSel osel) {

    constexpr int APL = 128 * 12;                       // words per A plane per stage
    constexpr int BPL = BNROWS ? 128 * 12 : 8 * 136;    // words per B plane per stage
    constexpr int STAGEW = 2 * APL + 2 * BPL;
    extern __shared__ __align__(16) uint32_t smem[];

    int rowBase = (TRIMK ? (gridDim.y - 1 - blockIdx.y) : blockIdx.y) * 128;
    int colBase = blockIdx.x * 128;
    if (EPI == 1 && colBase > rowBase) return;          // upper-tri scores blocks never read

    int bz = blockIdx.z;
    int bb = bz >> 3, hh = bz & 7;
    const uint32_t *Abh, *Abl, *Bbh, *Bbl;
    if (SELZ) {
        Abh = Ah; Abl = Al;
        Bbh = bsel.h[bz]; Bbl = bsel.l[bz];
    } else {
        long long ao = bb * sAb + hh * sAh_;
        long long bo = bb * sBb + hh * sBh_;
        Abh = Ah + ao; Abl = Al + ao;
        Bbh = Bh + bo; Bbl = Bl + bo;
    }

    int tid = threadIdx.x, lane = tid & 31, warp = tid >> 5;
    int g = lane >> 2, tig = lane & 3;
    int wm = warp >> 1, wn = warp & 1;

    float acc[2][8][4];
#pragma unroll
    for (int mt = 0; mt < 2; mt++)
#pragma unroll
        for (int nt = 0; nt < 8; nt++)
#pragma unroll
            for (int r = 0; r < 4; r++) acc[mt][nt][r] = 0.f;

    int Keff = TRIMK ? min(K, rowBase + 128) : K;
    const int T = Keff / 16;

    auto load_tile = [&](int t, int buf) {
        uint32_t* S   = smem + buf * STAGEW;
        uint32_t* SaH = S;            uint32_t* SaL = S + APL;
        uint32_t* SbH = S + 2 * APL;  uint32_t* SbL = SbH + BPL;
        int k0w = t * 8;
        {   // A: 128 rows x 8 words per plane; thread -> (row tid>>1, 16B half tid&1)
            int m = tid >> 1, kh = (tid & 1) * 4;
            long long src = (long long)(rowBase + m) * ldaw + k0w + kh;
            int dst = m * 12 + kh;
            cp16(SaH + dst, Abh + src);
            cp16(SaL + dst, Abl + src);
        }
        if (BNROWS) {   // B^T planes: [n][K/2 words]
            int n = tid >> 1, kh = (tid & 1) * 4;
            long long src = (long long)(colBase + n) * ldbw + k0w + kh;
            int dst = n * 12 + kh;
            cp16(SbH + dst, Bbh + src);
            cp16(SbL + dst, Bbl + src);
        } else {        // B planes: [K/2][N]; 8 pair-rows x 128 words
            int kk = tid >> 5, n4 = (tid & 31) * 4;
            long long src = (long long)(k0w + kk) * ldbw + colBase + n4;
            int dst = kk * 136 + n4;
            cp16(SbH + dst, Bbh + src);
            cp16(SbL + dst, Bbl + src);
        }
    };

    load_tile(0, 0); cp_commit();
    if (T > 1) { load_tile(1, 1); cp_commit(); }

    int buf = 0;
    for (int t = 0; t < T; t++) {
        if (t < T - 1) cp_wait1(); else cp_wait0();
        __syncthreads();
        if (t + 2 < T) { load_tile(t + 2, (buf + 2) % 3); cp_commit(); }

        const uint32_t* S   = smem + buf * STAGEW;
        const uint32_t* SaH = S;            const uint32_t* SaL = S + APL;
        const uint32_t* SbH = S + 2 * APL;  const uint32_t* SbL = SbH + BPL;

        uint32_t ah[2][4], al[2][4];
#pragma unroll
        for (int mt = 0; mt < 2; mt++) {
            int r0 = (wm * 32 + mt * 16 + g) * 12;
            int r1 = r0 + 8 * 12;
            ah[mt][0] = SaH[r0 + tig];     ah[mt][1] = SaH[r1 + tig];
            ah[mt][2] = SaH[r0 + tig + 4]; ah[mt][3] = SaH[r1 + tig + 4];
            al[mt][0] = SaL[r0 + tig];     al[mt][1] = SaL[r1 + tig];
            al[mt][2] = SaL[r0 + tig + 4]; al[mt][3] = SaL[r1 + tig + 4];
        }
#pragma unroll
        for (int nt = 0; nt < 8; nt++) {
            int n = wn * 64 + nt * 8 + g;
            uint32_t bh[2], bl[2];
            if (BNROWS) {
                bh[0] = SbH[n * 12 + tig];  bh[1] = SbH[n * 12 + tig + 4];
                bl[0] = SbL[n * 12 + tig];  bl[1] = SbL[n * 12 + tig + 4];
            } else {
                bh[0] = SbH[tig * 136 + n]; bh[1] = SbH[(tig + 4) * 136 + n];
                bl[0] = SbL[tig * 136 + n]; bl[1] = SbL[(tig + 4) * 136 + n];
            }
#pragma unroll
            for (int mt = 0; mt < 2; mt++) {
                mma_bf16(acc[mt][nt], ah[mt], bh);
                mma_bf16(acc[mt][nt], ah[mt], bl);
                mma_bf16(acc[mt][nt], al[mt], bh);
            }
        }
        __syncthreads();
        buf = (buf + 1) % 3;
    }

    float logg = 0.f;
    if (EPI == 1) {
        double lo = -3.4657359027997265;   // ln(1/32)
        double hi = -6.2383246250395077;   // ln(1/512)
        double gamma = 1.0 - exp(lo + (double)hh * ((hi - lo) / 7.0));
        logg = logf((float)gamma);
    }

    // output base selection
    float* Cfb = nullptr; uint32_t* Chb = nullptr; uint32_t* Clb = nullptr;
    bool planes = false;
    if (OUTP == 0) {
        Cfb = Cf + bb * sCb + hh * sCh_;
    } else if (OUTP == 1) {
        planes = true;
        long long co = bb * sCb + hh * sCh_;
        Chb = Ch + co; Clb = Cl + co;
    } else {
        if (bz < 2) { planes = true; Chb = osel.h[bz]; Clb = osel.l[bz]; }
        else        { Cfb = osel.f[bz]; }
    }

#pragma unroll
    for (int mt = 0; mt < 2; mt++) {
#pragma unroll
        for (int nt = 0; nt < 8; nt++) {
#pragma unroll
            for (int half = 0; half < 2; half++) {
                int r = rowBase + wm * 32 + mt * 16 + g + half * 8;
                int c = colBase + wn * 64 + nt * 8 + 2 * tig;
                float v0 = acc[mt][nt][half * 2 + 0];
                float v1 = acc[mt][nt][half * 2 + 1];
                if (EPI == 1) {
                    int d0 = r - c, d1 = r - (c + 1);
                    v0 = (d0 < 0) ? 0.f : v0 * expf((float)d0 * logg);
                    v1 = (d1 < 0) ? 0.f : v1 * expf((float)d1 * logg);
                } else if (EPI == 2) {
                    v0 += bias[c];
                    v1 += bias[c + 1];
                    float t0 = tanhf(0.7978845608028654f * (v0 + 0.044715f * v0 * v0 * v0));
                    float t1 = tanhf(0.7978845608028654f * (v1 + 0.044715f * v1 * v1 * v1));
                    v0 = 0.5f * v0 * (1.f + t0);
                    v1 = 0.5f * v1 * (1.f + t1);
                } else if (EPI == 3) {
                    float2 rr = *(const float2*)&resid[(size_t)r * ldc + c];
                    v0 += bias[c]     + rr.x;
                    v1 += bias[c + 1] + rr.y;
                } else if (EPI == 4) {
                    float2 rr = *(const float2*)&resid[(size_t)r * ldc + c];
                    v0 += rr.x;
                    v1 += rr.y;
                }
                if (planes) {
                    uint32_t hw, lw;
                    split2(v0, v1, hw, lw);
                    long long w = (long long)r * ldcw + (c >> 1);
                    Chb[w] = hw; Clb[w] = lw;
                } else {
                    *(float2*)&Cfb[(long long)r * ldc + c] = make_float2(v0, v1);
                }
            }
        }
    }
}

#define SMEM_STD (3 * (2 * 128 * 12 + 2 * 8 * 136) * 4)    // 62976 B
#define SMEM_BNR (3 * (2 * 128 * 12 + 2 * 128 * 12) * 4)   // 73728 B

// ---------------- host orchestration ----------------
extern "C" void kernel_launch(void* const* d_in, const int* in_sizes, int n_in,
                              void* d_out, int out_size) {
    (void)in_sizes; (void)n_in; (void)out_size;
    const float* x   = (const float*)d_in[0];
    const float* Wq  = (const float*)d_in[1];
    const float* Wk  = (const float*)d_in[2];
    const float* Wv  = (const float*)d_in[3];
    const float* Wg  = (const float*)d_in[4];
    const float* Wo  = (const float*)d_in[5];
    const float* gng = (const float*)d_in[6];
    const float* gnb = (const float*)d_in[7];
    const float* W1  = (const float*)d_in[8];
    const float* b1  = (const float*)d_in[9];
    const float* W2  = (const float*)d_in[10];
    const float* b2  = (const float*)d_in[11];
    const float* lng = (const float*)d_in[12];
    const float* lnb = (const float*)d_in[13];

    cudaFuncSetAttribute(gemm_kernel<0, false, true,  2, false>, cudaFuncAttributeMaxDynamicSharedMemorySize, SMEM_STD);
    cudaFuncSetAttribute(gemm_kernel<1, false, false, 1, true >, cudaFuncAttributeMaxDynamicSharedMemorySize, SMEM_BNR);
    cudaFuncSetAttribute(gemm_kernel<0, true,  false, 0, false>, cudaFuncAttributeMaxDynamicSharedMemorySize, SMEM_STD);
    cudaFuncSetAttribute(gemm_kernel<4, false, false, 0, false>, cudaFuncAttributeMaxDynamicSharedMemorySize, SMEM_STD);
    cudaFuncSetAttribute(gemm_kernel<2, false, false, 1, false>, cudaFuncAttributeMaxDynamicSharedMemorySize, SMEM_STD);
    cudaFuncSetAttribute(gemm_kernel<3, false, false, 0, false>, cudaFuncAttributeMaxDynamicSharedMemorySize, SMEM_STD);

    float *xb, *vv, *gt, *yy, *ret;
    uint32_t *xnh, *xnl, *qh, *ql, *kh, *kl, *vbh, *vbl, *sh, *sl, *yph, *ypl, *rnh, *rnl, *mh, *ml, *wh, *wl;
    cudaGetSymbolAddress((void**)&xb,  g_x);
    cudaGetSymbolAddress((void**)&vv,  g_v);
    cudaGetSymbolAddress((void**)&gt,  g_g);
    cudaGetSymbolAddress((void**)&yy,  g_y);
    cudaGetSymbolAddress((void**)&ret, g_ret);
    cudaGetSymbolAddress((void**)&xnh, g_xnh); cudaGetSymbolAddress((void**)&xnl, g_xnl);
    cudaGetSymbolAddress((void**)&qh,  g_qh);  cudaGetSymbolAddress((void**)&ql,  g_ql);
    cudaGetSymbolAddress((void**)&kh,  g_kh);  cudaGetSymbolAddress((void**)&kl,  g_kl);
    cudaGetSymbolAddress((void**)&vbh, g_vbh); cudaGetSymbolAddress((void**)&vbl, g_vbl);
    cudaGetSymbolAddress((void**)&sh,  g_sh);  cudaGetSymbolAddress((void**)&sl,  g_sl);
    cudaGetSymbolAddress((void**)&yph, g_yph); cudaGetSymbolAddress((void**)&ypl, g_ypl);
    cudaGetSymbolAddress((void**)&rnh, g_rnh); cudaGetSymbolAddress((void**)&rnl, g_rnl);
    cudaGetSymbolAddress((void**)&mh,  g_mh);  cudaGetSymbolAddress((void**)&ml,  g_ml);
    cudaGetSymbolAddress((void**)&wh,  g_wh);  cudaGetSymbolAddress((void**)&wl,  g_wl);

    BSel dummyB = {};
    OSel dummyO = {};

    // ---- weight split (all layers, once per call; deterministic) ----
    for (int i = 0; i < NLAYERS; i++) {
        size_t base = (size_t)i * WPL;
        const float* ws[5] = {Wq + (size_t)i*HID*HID, Wk + (size_t)i*HID*HID, Wv + (size_t)i*HID*HID,
                              Wg + (size_t)i*HID*HID, Wo + (size_t)i*HID*HID};
        for (int j = 0; j < 5; j++)
            wsplit_kernel<<<2048, 256>>>(ws[j], wh + base + (size_t)j*WQSZ, wl + base + (size_t)j*WQSZ,
                                         2048, 1024 * 512);
        wsplit_kernel<<<8192, 256>>>(W1 + (size_t)i*HID*FFDIM, wh + base + 5*(size_t)WQSZ,
                                     wl + base + 5*(size_t)WQSZ, 8192, 1024 * 2048);
        wsplit_kernel<<<8192, 256>>>(W2 + (size_t)i*FFDIM*HID, wh + base + 5*(size_t)WQSZ + W1SZ,
                                     wl + base + 5*(size_t)WQSZ + W1SZ, 2048, 4096 * 512);
    }

    cudaMemcpyAsync(xb, x, sizeof(float) * (size_t)NTOK * HID, cudaMemcpyDeviceToDevice);

    for (int i = 0; i < NLAYERS; i++) {
        size_t wbse = (size_t)i * WPL;
        const uint32_t* WqH = wh + wbse;            const uint32_t* WqL = wl + wbse;
        const uint32_t* WkH = WqH + WQSZ;           const uint32_t* WkL = WqL + WQSZ;
        const uint32_t* WvH = WqH + 2*WQSZ;         const uint32_t* WvL = WqL + 2*WQSZ;
        const uint32_t* WgH = WqH + 3*WQSZ;         const uint32_t* WgL = WqL + 3*WQSZ;
        const uint32_t* WoH = WqH + 4*WQSZ;         const uint32_t* WoL = WqL + 4*WQSZ;
        const uint32_t* W1H = WqH + 5*WQSZ;         const uint32_t* W1L = WqL + 5*WQSZ;
        const uint32_t* W2H = W1H + W1SZ;           const uint32_t* W2L = W1L + W1SZ;
        const float* b1i = b1 + (size_t)i * FFDIM;
        const float* b2i = b2 + (size_t)i * HID;
        const float* gngi = gng + (size_t)i * HID;
        const float* gnbi = gnb + (size_t)i * HID;

        // xn planes = LN(x)
        ln_split_kernel<<<NTOK, 256>>>(xb, lng, lnb, xnh, xnl);

        // fused QKVG: z0 -> q planes, z1 -> k planes, z2 -> v f32, z3 -> gate f32
        {
            BSel bs; OSel os = {};
            bs.h[0]=WqH; bs.h[1]=WkH; bs.h[2]=WvH; bs.h[3]=WgH;
            bs.l[0]=WqL; bs.l[1]=WkL; bs.l[2]=WvL; bs.l[3]=WgL;
            os.h[0]=qh; os.l[0]=ql; os.h[1]=kh; os.l[1]=kl;
            os.f[2]=vv; os.f[3]=gt;
            gemm_kernel<0, false, true, 2, false><<<dim3(16, 32, 4), 256, SMEM_STD>>>(
                xnh, xnl, nullptr, nullptr, nullptr, nullptr, nullptr,
                HID, 1024, 2048, 2048, 1024,
                0, 0, 0, 0, 0, 0, nullptr, nullptr, bs, os);
        }

        // v -> token-pair planes
        wsplit_kernel<<<4096, 256>>>(vv, vbh, vbl, 2048, 2048 * 512);

        // scores planes = (q . k^T) * decay   (upper blocks skipped; BNROWS B = k planes)
        gemm_kernel<1, false, false, 1, true><<<dim3(8, 8, 32), 256, SMEM_BNR>>>(
            qh, ql, kh, kl, nullptr, sh, sl,
            HEADDIM, 1024, 1024, 0, 512,
            (long long)SEQ * 1024, 128, (long long)SEQ * 1024, 128,
            (long long)8 * 1024 * 512, (long long)1024 * 512,
            nullptr, nullptr, dummyB, dummyO);

        // y f32 = scores @ v   (causal K-trim, heavy-rows-first)
        gemm_kernel<0, true, false, 0, false><<<dim3(2, 8, 32), 256, SMEM_STD>>>(
            sh, sl, vbh, vbl, yy, nullptr, nullptr,
            SEQ, 512, 2048, 2048, 0,
            (long long)8 * 1024 * 512, (long long)1024 * 512,
            (long long)512 * 2048, 256,
            (long long)SEQ * 2048, 256,
            nullptr, nullptr, dummyB, dummyO);

        // y' planes = silu(g) * GroupNorm(y)
        gn_gate_split_kernel<<<dim3(NTOK, NHEADS), 128>>>(yy, gt, gngi, gnbi, yph, ypl);

        // ret f32 = y' @ Wo + x
        gemm_kernel<4, false, false, 0, false><<<dim3(16, 32, 1), 256, SMEM_STD>>>(
            yph, ypl, WoH, WoL, ret, nullptr, nullptr,
            HID, 1024, 2048, 2048, 0,
            0, 0, 0, 0, 0, 0, nullptr, xb, dummyB, dummyO);

        // rn planes = LN(ret)
        ln_split_kernel<<<NTOK, 256>>>(ret, lng, lnb, rnh, rnl);

        // mid planes = gelu(rn @ W1 + b1)
        gemm_kernel<2, false, false, 1, false><<<dim3(64, 32, 1), 256, SMEM_STD>>>(
            rnh, rnl, W1H, W1L, nullptr, mh, ml,
            HID, 1024, 8192, 0, 4096,
            0, 0, 0, 0, 0, 0, b1i, nullptr, dummyB, dummyO);

        // x f32 = mid @ W2 + b2 + ret
        gemm_kernel<3, false, false, 0, false><<<dim3(16, 32, 1), 256, SMEM_STD>>>(
            mh, ml, W2H, W2L, xb, nullptr, nullptr,
            FFDIM, 4096, 2048, 2048, 0,
            0, 0, 0, 0, 0, 0, b2i, ret, dummyB, dummyO);
    }

    cudaMemcpyAsync(d_out, xb, sizeof(float) * (size_t)NTOK * HID, cudaMemcpyDeviceToDevice);
}